// round 10
// baseline (speedup 1.0000x reference)
#include <cuda_runtime.h>
#include <cstdint>

// Batched GEMM via mma.sync fp16 m16n8k16 + ldmatrix operand feeding.
// Round-10: rebalance registers/occupancy. 256 threads (8 warps), warp tile
// 64x32 -> acc 64 regs + prefetch 32 regs, fits 128-reg cap at 2 CTAs/SM
// (16 warps/SM, no spills). Same fp16-smem + ldmatrix pipeline as round 9.
//
//   x:    [B=16, M=256, K=512]  (K contiguous)
//   path: [B=16, K=512, N=2048] (N contiguous)
//   out:  [B=16, M=256, N=2048]
//
// CTA tile 128x128, BK=32, 2-stage double buffer, static smem 37.9 KB.

constexpr int Mm = 256, Kk = 512, Nn = 2048;
constexpr int BM = 128, BN = 128, BK = 32;
constexpr int THREADS = 256;
constexpr int KT = Kk / BK;  // 16

constexpr int A_STRIDE_H = 40;   // fp16 units (80B rows)
constexpr int B_STRIDE_H = 136;  // fp16 units (272B rows)
constexpr int A_STAGE_B = BM * A_STRIDE_H * 2;   // 10240 B
constexpr int B_STAGE_B = BK * B_STRIDE_H * 2;   // 8704 B
constexpr int STAGE_B   = A_STAGE_B + B_STAGE_B; // 18944 B

__device__ __forceinline__ uint32_t smem_u32(const void* ptr) {
    uint32_t a;
    asm("{ .reg .u64 t; cvta.to.shared.u64 t, %1; cvt.u32.u64 %0, t; }"
        : "=r"(a) : "l"(ptr));
    return a;
}

// pack two fp32 into f16x2: lo half = first arg, hi half = second arg
__device__ __forceinline__ uint32_t h2pack(float lo, float hi) {
    uint32_t r;
    asm("cvt.rn.f16x2.f32 %0, %1, %2;" : "=r"(r) : "f"(hi), "f"(lo));
    return r;
}

__device__ __forceinline__ void ldmatrix_x4(uint32_t& r0, uint32_t& r1,
                                            uint32_t& r2, uint32_t& r3, uint32_t addr) {
    asm volatile("ldmatrix.sync.aligned.m8n8.x4.shared.b16 {%0,%1,%2,%3}, [%4];"
                 : "=r"(r0), "=r"(r1), "=r"(r2), "=r"(r3) : "r"(addr));
}
__device__ __forceinline__ void ldmatrix_x4_trans(uint32_t& r0, uint32_t& r1,
                                                  uint32_t& r2, uint32_t& r3, uint32_t addr) {
    asm volatile("ldmatrix.sync.aligned.m8n8.x4.trans.shared.b16 {%0,%1,%2,%3}, [%4];"
                 : "=r"(r0), "=r"(r1), "=r"(r2), "=r"(r3) : "r"(addr));
}

__device__ __forceinline__ void mma_f16(float& c0, float& c1, float& c2, float& c3,
                                        uint32_t a0, uint32_t a1, uint32_t a2, uint32_t a3,
                                        uint32_t b0, uint32_t b1) {
    asm volatile(
        "mma.sync.aligned.m16n8k16.row.col.f32.f16.f16.f32 "
        "{%0,%1,%2,%3}, {%4,%5,%6,%7}, {%8,%9}, {%0,%1,%2,%3};"
        : "+f"(c0), "+f"(c1), "+f"(c2), "+f"(c3)
        : "r"(a0), "r"(a1), "r"(a2), "r"(a3), "r"(b0), "r"(b1));
}

__global__ __launch_bounds__(THREADS, 2)
void bmm_mma_f16_ldm8(const float* __restrict__ A,
                      const float* __restrict__ B,
                      float* __restrict__ C) {
    __shared__ __align__(16) char smem_raw[2 * STAGE_B];
    const uint32_t sb = smem_u32(smem_raw);

    const int tid = threadIdx.x;
    const int wid = tid >> 5;
    const int lane = tid & 31;
    const int b  = blockIdx.z;
    const int by = blockIdx.y;
    const int n0 = blockIdx.x * BN;

    const float* Ab = A + (size_t)b * Mm * Kk + (size_t)by * BM * Kk;
    const float* Bb = B + (size_t)b * Kk * Nn + n0;
    float*       Cb = C + (size_t)b * Mm * Nn + (size_t)by * BM * Nn + n0;

    // ---- staging mappings: 4 float4 chunks each of A and B per thread ----
    // A tile: 128 rows x 32 floats -> chunk i: row = i>>3, kq = (i&7)*4
    // B tile: 32 rows x 128 floats -> chunk i: krow = i>>5, n = (i&31)*4
    const float* aSrc[4];
    const float* bSrc[4];
    uint32_t aOff[4], bOff[4];
#pragma unroll
    for (int j = 0; j < 4; j++) {
        int i = j * 256 + tid;
        int row = i >> 3, kq = (i & 7) * 4;
        aSrc[j] = Ab + (size_t)row * Kk + kq;
        aOff[j] = row * (A_STRIDE_H * 2) + kq * 2;
        int krow = i >> 5, n = (i & 31) * 4;
        bSrc[j] = Bb + (size_t)krow * Nn + n;
        bOff[j] = A_STAGE_B + krow * (B_STRIDE_H * 2) + n * 2;
    }

    float4 aR[4], bR[4];

    auto ldg_stage = [&](int kt) {
#pragma unroll
        for (int j = 0; j < 4; j++) aR[j] = *(const float4*)(aSrc[j] + (size_t)kt * BK);
#pragma unroll
        for (int j = 0; j < 4; j++) bR[j] = *(const float4*)(bSrc[j] + (size_t)kt * BK * Nn);
    };
    auto sts_stage = [&](int s) {
        const uint32_t soff = s * STAGE_B;
#pragma unroll
        for (int j = 0; j < 4; j++) {
            uint2 p = make_uint2(h2pack(aR[j].x, aR[j].y), h2pack(aR[j].z, aR[j].w));
            *(uint2*)(smem_raw + aOff[j] + soff) = p;
        }
#pragma unroll
        for (int j = 0; j < 4; j++) {
            uint2 p = make_uint2(h2pack(bR[j].x, bR[j].y), h2pack(bR[j].z, bR[j].w));
            *(uint2*)(smem_raw + bOff[j] + soff) = p;
        }
    };

    // ---- compute mapping: 8 warps, 2x4 of 64x32 warp tiles ----
    const int warp_m = wid >> 2;        // 0..1
    const int warp_n = wid & 3;         // 0..3
    const int m_base = warp_m * 64;
    const int nb     = warp_n * 32;
    const int g = lane >> 2;
    const int t = lane & 3;

    // ldmatrix lane-address components
    const int lrow8 = (lane & 7) + ((lane >> 3) & 1) * 8;  // row within 16
    const int lk8   = ((lane >> 4) & 1) * 8;               // k/n half select

    float acc[4][4][4];
#pragma unroll
    for (int i = 0; i < 4; i++)
#pragma unroll
        for (int j = 0; j < 4; j++)
#pragma unroll
            for (int r = 0; r < 4; r++) acc[i][j][r] = 0.0f;

    // prologue
    ldg_stage(0);
    sts_stage(0);
    __syncthreads();

#pragma unroll 1
    for (int kt = 0; kt < KT; kt++) {
        const int cur = kt & 1;

        if (kt + 1 < KT) ldg_stage(kt + 1);

        const uint32_t Abase = sb + cur * STAGE_B;
        const uint32_t Bbase = Abase + A_STAGE_B;

#pragma unroll
        for (int ks = 0; ks < 2; ks++) {     // 2 x k16 per BK=32
            const int k0 = ks * 16;

            uint32_t af[4][4];
#pragma unroll
            for (int i = 0; i < 4; i++) {
                uint32_t addr = Abase
                    + (m_base + i * 16 + lrow8) * (A_STRIDE_H * 2)
                    + (k0 + lk8) * 2;
                ldmatrix_x4(af[i][0], af[i][1], af[i][2], af[i][3], addr);
            }
            uint32_t bf[2][4];  // [n16 tile][r0=b0 lo, r1=b1 lo, r2=b0 hi, r3=b1 hi]
#pragma unroll
            for (int j2 = 0; j2 < 2; j2++) {
                uint32_t addr = Bbase
                    + (k0 + lrow8) * (B_STRIDE_H * 2)
                    + (nb + j2 * 16 + lk8) * 2;
                ldmatrix_x4_trans(bf[j2][0], bf[j2][1], bf[j2][2], bf[j2][3], addr);
            }
#pragma unroll
            for (int i = 0; i < 4; i++)
#pragma unroll
                for (int j = 0; j < 4; j++) {
                    const int j2 = j >> 1, h = (j & 1) * 2;
                    mma_f16(acc[i][j][0], acc[i][j][1], acc[i][j][2], acc[i][j][3],
                            af[i][0], af[i][1], af[i][2], af[i][3],
                            bf[j2][h + 0], bf[j2][h + 1]);
                }
        }

        if (kt + 1 < KT) sts_stage(cur ^ 1);
        __syncthreads();
    }

    // ---- epilogue (standard m16n8 C layout) ----
#pragma unroll
    for (int i = 0; i < 4; i++) {
        const int row0 = m_base + i * 16 + g;
#pragma unroll
        for (int j = 0; j < 4; j++) {
            const int col = nb + j * 8 + 2 * t;
            *(float2*)(Cb + (size_t)row0 * Nn + col) =
                make_float2(acc[i][j][0], acc[i][j][1]);
            *(float2*)(Cb + (size_t)(row0 + 8) * Nn + col) =
                make_float2(acc[i][j][2], acc[i][j][3]);
        }
    }
}

extern "C" void kernel_launch(void* const* d_in, const int* in_sizes, int n_in,
                              void* d_out, int out_size) {
    const float* x    = (const float*)d_in[0];  // [16, 256, 512]
    const float* path = (const float*)d_in[1];  // [16, 512, 2048]
    float* out = (float*)d_out;                 // [16, 256, 2048]

    dim3 grid(Nn / BN, Mm / BM, 16);  // (16, 2, 16) = 512 CTAs
    bmm_mma_f16_ldm8<<<grid, THREADS>>>(x, path, out);
}